// round 12
// baseline (speedup 1.0000x reference)
#include <cuda_runtime.h>
#include <cuda_bf16.h>
#include <math.h>
#include <stdint.h>

// Problem constants
#define Bn 2
#define Tn 2048
#define Cn 1024
#define Hn 16
#define HSn 64
#define FFn 4096
#define EPSn 1e-5f
#define NEG_BIG (-1e30f)
#define Mrows (Bn * Tn)   // 4096
#define QKVS (3 * Cn)     // fused qkv row stride

// ===========================================================================
// PTX helpers (generic sm_80+ only)
// ===========================================================================
__device__ __forceinline__ uint32_t smem_u32(const void* p) {
    uint32_t a;
    asm("{ .reg .u64 t; cvta.to.shared.u64 t, %1; cvt.u32.u64 %0, t; }" : "=r"(a) : "l"(p));
    return a;
}

#define CP_ASYNC16(dst, src) \
    asm volatile("cp.async.cg.shared.global [%0], [%1], 16;" :: "r"(dst), "l"(src))
#define CP_ASYNC_COMMIT() asm volatile("cp.async.commit_group;" ::: "memory")
#define CP_ASYNC_WAIT0() asm volatile("cp.async.wait_group 0;" ::: "memory")
#define CP_ASYNC_WAIT1() asm volatile("cp.async.wait_group 1;" ::: "memory")

__device__ __forceinline__ void ldsm4(uint32_t r[4], uint32_t addr) {
    asm volatile("ldmatrix.sync.aligned.m8n8.x4.shared.b16 {%0,%1,%2,%3}, [%4];"
                 : "=r"(r[0]), "=r"(r[1]), "=r"(r[2]), "=r"(r[3]) : "r"(addr));
}
__device__ __forceinline__ void ldsm4t(uint32_t r[4], uint32_t addr) {
    asm volatile("ldmatrix.sync.aligned.m8n8.x4.trans.shared.b16 {%0,%1,%2,%3}, [%4];"
                 : "=r"(r[0]), "=r"(r[1]), "=r"(r[2]), "=r"(r[3]) : "r"(addr));
}

__device__ __forceinline__ void mma16816(float c[4], const uint32_t a[4],
                                         uint32_t b0, uint32_t b1) {
    asm volatile(
        "mma.sync.aligned.m16n8k16.row.col.f32.bf16.bf16.f32 "
        "{%0,%1,%2,%3}, {%4,%5,%6,%7}, {%8,%9}, {%0,%1,%2,%3};"
        : "+f"(c[0]), "+f"(c[1]), "+f"(c[2]), "+f"(c[3])
        : "r"(a[0]), "r"(a[1]), "r"(a[2]), "r"(a[3]), "r"(b0), "r"(b1));
}

__device__ __forceinline__ uint32_t sw64(uint32_t b) { return b ^ ((b >> 3) & 0x30u); }
__device__ __forceinline__ uint32_t sw128(uint32_t b) { return b ^ ((b >> 3) & 0x70u); }

// ===========================================================================
// Device scratch
// ===========================================================================
__device__ __align__(256) __nv_bfloat16 g_xh[Mrows * Cn], g_xl[Mrows * Cn];
__device__ __align__(256) __nv_bfloat16 g_Wqkvth[3 * Cn * Cn], g_Wqkvtl[3 * Cn * Cn];
__device__ __align__(256) __nv_bfloat16 g_Wpth[Cn * Cn], g_Wptl[Cn * Cn];
__device__ __align__(256) __nv_bfloat16 g_W1th[FFn * Cn], g_W1tl[FFn * Cn];
__device__ __align__(256) __nv_bfloat16 g_W2th[Cn * FFn], g_W2tl[Cn * FFn];
__device__ __align__(256) float g_bqkv[3 * Cn];
__device__ __align__(256) __nv_bfloat16 g_qkvh[Mrows * 3 * Cn], g_qkvl[Mrows * 3 * Cn];
__device__ __align__(256) __nv_bfloat16 g_atth[Mrows * Cn], g_attl[Mrows * Cn];
__device__ __align__(256) __nv_bfloat16 g_hh[Mrows * Cn], g_hl[Mrows * Cn];
__device__ __align__(256) __nv_bfloat16 g_f1h[Mrows * FFn], g_f1l[Mrows * FFn];
__device__ __align__(256) float g_t0[Mrows * Cn];
__device__ __align__(256) float g_f2[Mrows * Cn];

// ===========================================================================
// Elementwise split (vectorized x4): fp32 -> (hi, lo) bf16
// ===========================================================================
__global__ void split_kernel(const float* __restrict__ in, __nv_bfloat16* __restrict__ oh,
                             __nv_bfloat16* __restrict__ ol) {
    int i = (blockIdx.x * 256 + threadIdx.x) * 4;
    float4 v = *(const float4*)&in[i];
    __nv_bfloat162 h01 = __floats2bfloat162_rn(v.x, v.y);
    __nv_bfloat162 h23 = __floats2bfloat162_rn(v.z, v.w);
    __nv_bfloat162 l01 = __floats2bfloat162_rn(v.x - __bfloat162float(h01.x),
                                               v.y - __bfloat162float(h01.y));
    __nv_bfloat162 l23 = __floats2bfloat162_rn(v.z - __bfloat162float(h23.x),
                                               v.w - __bfloat162float(h23.y));
    uint2 hp; hp.x = *(uint32_t*)&h01; hp.y = *(uint32_t*)&h23;
    uint2 lp; lp.x = *(uint32_t*)&l01; lp.y = *(uint32_t*)&l23;
    *(uint2*)&oh[i] = hp;
    *(uint2*)&ol[i] = lp;
}

// ===========================================================================
// Tiled transpose+split (generic, used for Wp/W1/W2)
// ===========================================================================
__global__ void transpose_split(const float* __restrict__ in, __nv_bfloat16* __restrict__ oh,
                                __nv_bfloat16* __restrict__ ol, int R, int Cc) {
    __shared__ float tile[32][33];
    size_t boff = (size_t)blockIdx.z * R * Cc;
    const float* ip = in + boff;
    int i0 = blockIdx.y * 32, j0 = blockIdx.x * 32;
#pragma unroll
    for (int k = threadIdx.y; k < 32; k += 8)
        tile[k][threadIdx.x] = ip[(size_t)(i0 + k) * Cc + j0 + threadIdx.x];
    __syncthreads();
#pragma unroll
    for (int k = threadIdx.y; k < 32; k += 8) {
        float v = tile[threadIdx.x][k];
        __nv_bfloat16 h = __float2bfloat16(v);
        size_t o = boff + (size_t)(j0 + k) * R + i0 + threadIdx.x;
        oh[o] = h;
        ol[o] = __float2bfloat16(v - __bfloat162float(h));
    }
}

// ===========================================================================
// Fused QKV weight transpose+split + bias concat.
// ===========================================================================
__global__ void transpose_split_qkv(const float* __restrict__ Wq, const float* __restrict__ Wk,
                                    const float* __restrict__ Wv,
                                    const float* __restrict__ bq, const float* __restrict__ bk,
                                    const float* __restrict__ bv,
                                    __nv_bfloat16* __restrict__ oh, __nv_bfloat16* __restrict__ ol,
                                    float* __restrict__ bqkv) {
    __shared__ float tile[32][33];
    int w = blockIdx.z / Hn;
    int hz = blockIdx.z % Hn;
    const float* Win = (w == 0) ? Wq : (w == 1) ? Wk : Wv;
    const float* bin = (w == 0) ? bq : (w == 1) ? bk : bv;
    const float* ip = Win + (size_t)hz * Cn * HSn;
    __nv_bfloat16* poh = oh + (size_t)w * Cn * Cn + (size_t)hz * HSn * Cn;
    __nv_bfloat16* pol = ol + (size_t)w * Cn * Cn + (size_t)hz * HSn * Cn;

    if (blockIdx.x == 0 && blockIdx.y == 0 && hz == 0) {
        int t = threadIdx.y * 32 + threadIdx.x;
#pragma unroll
        for (int i = 0; i < 4; i++) bqkv[w * Cn + t + i * 256] = bin[t + i * 256];
    }

    int i0 = blockIdx.y * 32, j0 = blockIdx.x * 32;
#pragma unroll
    for (int k = threadIdx.y; k < 32; k += 8)
        tile[k][threadIdx.x] = ip[(size_t)(i0 + k) * HSn + j0 + threadIdx.x];
    __syncthreads();
#pragma unroll
    for (int k = threadIdx.y; k < 32; k += 8) {
        float v = tile[threadIdx.x][k];
        __nv_bfloat16 h = __float2bfloat16(v);
        size_t o = (size_t)(j0 + k) * Cn + i0 + threadIdx.x;
        poh[o] = h;
        pol[o] = __float2bfloat16(v - __bfloat162float(h));
    }
}

// ===========================================================================
// Tensor-core GEMM via mma.sync, bf16 hi/lo split (3-term fp32 emulation).
// CTA 128x128, 8 warps (4Mx2N), K-chunk 32, 3-stage cp.async, 2 CTAs/SM.
// ===========================================================================
#define STAGE_BYTES 32768
#define GEMM_SMEM (3 * STAGE_BYTES)

template <bool SPLIT, bool RELU>
__global__ void __launch_bounds__(256, 2)
gemm_mma(const __nv_bfloat16* __restrict__ Ahi, const __nv_bfloat16* __restrict__ Alo,
         const __nv_bfloat16* __restrict__ Bhi, const __nv_bfloat16* __restrict__ Blo,
         const float* __restrict__ bias,
         float* __restrict__ Cf, __nv_bfloat16* __restrict__ Chi, __nv_bfloat16* __restrict__ Clo,
         int M, int N, int K) {
    extern __shared__ char dsmem[];
    uint32_t sb = smem_u32(dsmem);

    int tid = threadIdx.x;
    int wid = tid >> 5;
    int lane = tid & 31;
    int n0 = blockIdx.x * 128;
    int m0 = blockIdx.y * 128;
    int wm = wid & 3;
    int wn = wid >> 2;

    const int NC = K >> 5;

    auto load_chunk = [&](int c, int stage) {
        uint32_t base = sb + (uint32_t)stage * STAGE_BYTES;
        size_t kof = (size_t)c * 32;
#pragma unroll
        for (int i = 0; i < 8; i++) {
            int g = i * 256 + tid;
            int tilei = g >> 9;
            int idx = g & 511;
            int row = idx >> 2;
            int ch = idx & 3;
            const __nv_bfloat16* src;
            if (tilei == 0)      src = Ahi + (size_t)(m0 + row) * K + kof + ch * 8;
            else if (tilei == 1) src = Alo + (size_t)(m0 + row) * K + kof + ch * 8;
            else if (tilei == 2) src = Bhi + (size_t)(n0 + row) * K + kof + ch * 8;
            else                 src = Blo + (size_t)(n0 + row) * K + kof + ch * 8;
            uint32_t dst = base + (uint32_t)tilei * 8192u + sw64((uint32_t)(row * 64 + ch * 16));
            CP_ASYNC16(dst, src);
        }
        CP_ASYNC_COMMIT();
    };

    float c[2][8][4];
#pragma unroll
    for (int mt = 0; mt < 2; mt++)
#pragma unroll
        for (int nt = 0; nt < 8; nt++)
#pragma unroll
            for (int j = 0; j < 4; j++) c[mt][nt][j] = 0.f;

    load_chunk(0, 0);
    load_chunk(1, 1);

    int arow = lane & 15;
    int aoff = (lane >> 4) * 16;
    int brow = ((lane >> 4) << 3) + (lane & 7);
    int boff = ((lane >> 3) & 1) * 16;

    for (int cc = 0; cc < NC; cc++) {
        if (cc == NC - 1) { CP_ASYNC_WAIT0(); } else { CP_ASYNC_WAIT1(); }
        __syncthreads();
        if (cc + 2 < NC) load_chunk(cc + 2, (cc + 2) % 3);

        uint32_t base = sb + (uint32_t)(cc % 3) * STAGE_BYTES;
#pragma unroll
        for (int k16 = 0; k16 < 2; k16++) {
            uint32_t ahi[2][4], alo[2][4];
#pragma unroll
            for (int mt = 0; mt < 2; mt++) {
                uint32_t byte = (uint32_t)((wm * 32 + mt * 16 + arow) * 64 + k16 * 32 + aoff);
                uint32_t sw = sw64(byte);
                ldsm4(ahi[mt], base + sw);
                ldsm4(alo[mt], base + 8192u + sw);
            }
#pragma unroll
            for (int nt16 = 0; nt16 < 4; nt16++) {
                uint32_t byte = (uint32_t)((wn * 64 + nt16 * 16 + brow) * 64 + k16 * 32 + boff);
                uint32_t sw = sw64(byte);
                uint32_t bh[4], bl[4];
                ldsm4(bh, base + 16384u + sw);
                ldsm4(bl, base + 24576u + sw);
#pragma unroll
                for (int term = 0; term < 3; term++) {
#pragma unroll
                    for (int half = 0; half < 2; half++) {
                        int nt = nt16 * 2 + half;
#pragma unroll
                        for (int mt = 0; mt < 2; mt++) {
                            if (term == 0)      mma16816(c[mt][nt], ahi[mt], bh[half * 2], bh[half * 2 + 1]);
                            else if (term == 1) mma16816(c[mt][nt], ahi[mt], bl[half * 2], bl[half * 2 + 1]);
                            else                mma16816(c[mt][nt], alo[mt], bh[half * 2], bh[half * 2 + 1]);
                        }
                    }
                }
            }
        }
    }

    int mbase = m0 + wm * 32;
    int nbase = n0 + wn * 64;
#pragma unroll
    for (int mt = 0; mt < 2; mt++) {
#pragma unroll
        for (int nt = 0; nt < 8; nt++) {
            int row0 = mbase + mt * 16 + (lane >> 2);
            int col = nbase + nt * 8 + (lane & 3) * 2;
            float b0 = bias[col], b1 = bias[col + 1];
#pragma unroll
            for (int half = 0; half < 2; half++) {
                int row = row0 + half * 8;
                float v0 = c[mt][nt][half * 2 + 0] + b0;
                float v1 = c[mt][nt][half * 2 + 1] + b1;
                if (RELU) { v0 = fmaxf(v0, 0.f); v1 = fmaxf(v1, 0.f); }
                if (SPLIT) {
                    __nv_bfloat16 h0 = __float2bfloat16(v0);
                    __nv_bfloat16 h1 = __float2bfloat16(v1);
                    __nv_bfloat162 hp; hp.x = h0; hp.y = h1;
                    __nv_bfloat162 lp;
                    lp.x = __float2bfloat16(v0 - __bfloat162float(h0));
                    lp.y = __float2bfloat16(v1 - __bfloat162float(h1));
                    *(__nv_bfloat162*)&Chi[(size_t)row * N + col] = hp;
                    *(__nv_bfloat162*)&Clo[(size_t)row * N + col] = lp;
                } else {
                    float2 r; r.x = v0; r.y = v1;
                    *(float2*)&Cf[(size_t)row * N + col] = r;
                }
            }
        }
    }
}

// ===========================================================================
// Tensor-core flash attention, bf16 split emulation, double-buffered KV.
// Q-hi AND Q-lo fragments held in registers; base-2 softmax.
// ===========================================================================
#define ATT_SMEM 98304

__global__ void __launch_bounds__(256, 2) attn_mma(
    const __nv_bfloat16* __restrict__ QKVh, const __nv_bfloat16* __restrict__ QKVl,
    __nv_bfloat16* __restrict__ Oh, __nv_bfloat16* __restrict__ Ol) {
    extern __shared__ char dsmem[];
    uint32_t sbQ = smem_u32(dsmem);
    uint32_t sbKV = sbQ + 32768u;

    int tid = threadIdx.x;
    int wid = tid >> 5;
    int lane = tid & 31;
    int q0 = ((int)gridDim.x - 1 - (int)blockIdx.x) * 128;   // heavy tiles first
    int h = blockIdx.y;
    int b = blockIdx.z;

    const __nv_bfloat16* Qhg = QKVh + ((size_t)(b * Tn + q0)) * QKVS + h * HSn;
    const __nv_bfloat16* Qlg = QKVl + ((size_t)(b * Tn + q0)) * QKVS + h * HSn;
    const __nv_bfloat16* Khg = QKVh + ((size_t)(b * Tn)) * QKVS + Cn + h * HSn;
    const __nv_bfloat16* Klg = QKVl + ((size_t)(b * Tn)) * QKVS + Cn + h * HSn;
    const __nv_bfloat16* Vhg = QKVh + ((size_t)(b * Tn)) * QKVS + 2 * Cn + h * HSn;
    const __nv_bfloat16* Vlg = QKVl + ((size_t)(b * Tn)) * QKVS + 2 * Cn + h * HSn;

    auto load_kv = [&](int t) {
        int s0 = t * 64;
        uint32_t stb = sbKV + (uint32_t)(t & 1) * 32768u;
#pragma unroll
        for (int i = 0; i < 8; i++) {
            int g = i * 256 + tid;
            int mat = g >> 9;
            int idx = g & 511;
            int row = idx >> 3;
            int ch = idx & 7;
            const __nv_bfloat16* src;
            if (mat == 0)      src = Khg + (size_t)(s0 + row) * QKVS + ch * 8;
            else if (mat == 1) src = Klg + (size_t)(s0 + row) * QKVS + ch * 8;
            else if (mat == 2) src = Vhg + (size_t)(s0 + row) * QKVS + ch * 8;
            else               src = Vlg + (size_t)(s0 + row) * QKVS + ch * 8;
            CP_ASYNC16(stb + (uint32_t)mat * 8192u + sw128((uint32_t)(row * 128 + ch * 16)), src);
        }
        CP_ASYNC_COMMIT();
    };

    // Q (hi/lo) load in its own group, then first KV tile
#pragma unroll
    for (int i = 0; i < 8; i++) {
        int g = i * 256 + tid;
        int hilo = g >> 10;
        int idx = g & 1023;
        int row = idx >> 3;
        int ch = idx & 7;
        const __nv_bfloat16* src = (hilo ? Qlg : Qhg) + (size_t)row * QKVS + ch * 8;
        CP_ASYNC16(sbQ + (uint32_t)hilo * 16384u + sw128((uint32_t)(row * 128 + ch * 16)), src);
    }
    CP_ASYNC_COMMIT();
    load_kv(0);

    int arow = lane & 15;
    int aoff = (lane >> 4) * 16;
    int brow = ((lane >> 4) << 3) + (lane & 7);
    int boff = ((lane >> 3) & 1) * 16;
    int vrow = ((lane >> 3) & 1) * 8 + (lane & 7);
    int vcol = (lane >> 4) * 8;

    // Wait Q group, then hold Q-hi AND Q-lo frags in registers
    CP_ASYNC_WAIT1();
    __syncthreads();
    uint32_t qfh[4][4], qfl[4][4];
#pragma unroll
    for (int kk = 0; kk < 4; kk++) {
        uint32_t abyte = (uint32_t)((wid * 16 + arow) * 128 + kk * 32 + aoff);
        ldsm4(qfh[kk], sbQ + sw128(abyte));
        ldsm4(qfl[kk], sbQ + 16384u + sw128(abyte));
    }

    float m0s = NEG_BIG, m1s = NEG_BIG, l0 = 0.f, l1 = 0.f;
    float co[8][4];
#pragma unroll
    for (int nt = 0; nt < 8; nt++)
#pragma unroll
        for (int j = 0; j < 4; j++) co[nt][j] = 0.f;

    int rw = q0 + wid * 16;
    int r0 = rw + (lane >> 2);
    int nkt = q0 / 64 + 2;
    const float scale2 = 0.125f * 1.44269504089f;   // base-2 softmax

    for (int t = 0; t < nkt; t++) {
        __syncthreads();
        if (t + 1 < nkt) { load_kv(t + 1); CP_ASYNC_WAIT1(); }
        else             { CP_ASYNC_WAIT0(); }
        __syncthreads();

        int s0 = t * 64;
        uint32_t sbK = sbKV + (uint32_t)(t & 1) * 32768u;
        uint32_t sbV = sbK + 16384u;

        if (s0 <= rw + 15) {
            float sp[8][4];
#pragma unroll
            for (int nt = 0; nt < 8; nt++)
#pragma unroll
                for (int j = 0; j < 4; j++) sp[nt][j] = 0.f;

#pragma unroll
            for (int kk = 0; kk < 4; kk++) {
#pragma unroll
                for (int nt16 = 0; nt16 < 4; nt16++) {
                    uint32_t bbyte = (uint32_t)((nt16 * 16 + brow) * 128 + kk * 32 + boff);
                    uint32_t bH[4], bL[4];
                    ldsm4(bH, sbK + sw128(bbyte));
                    ldsm4(bL, sbK + 8192u + sw128(bbyte));
#pragma unroll
                    for (int term = 0; term < 3; term++) {
#pragma unroll
                        for (int half = 0; half < 2; half++) {
                            int nt = nt16 * 2 + half;
                            if (term == 0)      mma16816(sp[nt], qfh[kk], bH[half * 2], bH[half * 2 + 1]);
                            else if (term == 1) mma16816(sp[nt], qfh[kk], bL[half * 2], bL[half * 2 + 1]);
                            else                mma16816(sp[nt], qfl[kk], bH[half * 2], bH[half * 2 + 1]);
                        }
                    }
                }
            }

            bool diag = (s0 + 63 > rw);
            float mx0 = NEG_BIG, mx1 = NEG_BIG;
#pragma unroll
            for (int nt = 0; nt < 8; nt++) {
                float c0 = sp[nt][0] * scale2;
                float c1 = sp[nt][1] * scale2;
                float c2 = sp[nt][2] * scale2;
                float c3 = sp[nt][3] * scale2;
                if (diag) {
                    int cg = s0 + nt * 8 + (lane & 3) * 2;
                    if (cg > r0) c0 = NEG_BIG;
                    if (cg + 1 > r0) c1 = NEG_BIG;
                    if (cg > r0 + 8) c2 = NEG_BIG;
                    if (cg + 1 > r0 + 8) c3 = NEG_BIG;
                }
                sp[nt][0] = c0; sp[nt][1] = c1; sp[nt][2] = c2; sp[nt][3] = c3;
                mx0 = fmaxf(mx0, fmaxf(c0, c1));
                mx1 = fmaxf(mx1, fmaxf(c2, c3));
            }
            mx0 = fmaxf(mx0, __shfl_xor_sync(0xffffffffu, mx0, 1));
            mx0 = fmaxf(mx0, __shfl_xor_sync(0xffffffffu, mx0, 2));
            mx1 = fmaxf(mx1, __shfl_xor_sync(0xffffffffu, mx1, 1));
            mx1 = fmaxf(mx1, __shfl_xor_sync(0xffffffffu, mx1, 2));

            float mn0 = fmaxf(m0s, mx0), mn1 = fmaxf(m1s, mx1);
            float al0 = exp2f(m0s - mn0), al1 = exp2f(m1s - mn1);
            m0s = mn0; m1s = mn1;

            float ps0 = 0.f, ps1 = 0.f;
#pragma unroll
            for (int nt = 0; nt < 8; nt++) {
                float p0 = exp2f(sp[nt][0] - mn0);
                float p1 = exp2f(sp[nt][1] - mn0);
                float p2 = exp2f(sp[nt][2] - mn1);
                float p3 = exp2f(sp[nt][3] - mn1);
                ps0 += p0 + p1; ps1 += p2 + p3;
                sp[nt][0] = p0; sp[nt][1] = p1; sp[nt][2] = p2; sp[nt][3] = p3;
            }
            ps0 += __shfl_xor_sync(0xffffffffu, ps0, 1);
            ps0 += __shfl_xor_sync(0xffffffffu, ps0, 2);
            ps1 += __shfl_xor_sync(0xffffffffu, ps1, 1);
            ps1 += __shfl_xor_sync(0xffffffffu, ps1, 2);
            l0 = l0 * al0 + ps0;
            l1 = l1 * al1 + ps1;
#pragma unroll
            for (int nt = 0; nt < 8; nt++) {
                co[nt][0] *= al0; co[nt][1] *= al0;
                co[nt][2] *= al1; co[nt][3] *= al1;
            }

#pragma unroll
            for (int kk = 0; kk < 4; kk++) {
                uint32_t aPh[4], aPl[4];
#pragma unroll
                for (int q = 0; q < 2; q++) {
                    int nt = 2 * kk + q;
#pragma unroll
                    for (int rr = 0; rr < 2; rr++) {
                        float v0 = sp[nt][rr * 2 + 0];
                        float v1 = sp[nt][rr * 2 + 1];
                        __nv_bfloat162 hp = __floats2bfloat162_rn(v0, v1);
                        float r0f = v0 - __bfloat162float(hp.x);
                        float r1f = v1 - __bfloat162float(hp.y);
                        __nv_bfloat162 lp = __floats2bfloat162_rn(r0f, r1f);
                        aPh[q * 2 + rr] = *(uint32_t*)&hp;
                        aPl[q * 2 + rr] = *(uint32_t*)&lp;
                    }
                }
#pragma unroll
                for (int dnt16 = 0; dnt16 < 4; dnt16++) {
                    uint32_t vbyte = (uint32_t)((kk * 16 + vrow) * 128 + (dnt16 * 16 + vcol) * 2);
                    uint32_t vH[4], vL[4];
                    ldsm4t(vH, sbV + sw128(vbyte));
                    ldsm4t(vL, sbV + 8192u + sw128(vbyte));
#pragma unroll
                    for (int term = 0; term < 3; term++) {
#pragma unroll
                        for (int half = 0; half < 2; half++) {
                            int dn = dnt16 * 2 + half;
                            if (term == 0)      mma16816(co[dn], aPh, vH[half * 2], vH[half * 2 + 1]);
                            else if (term == 1) mma16816(co[dn], aPh, vL[half * 2], vL[half * 2 + 1]);
                            else                mma16816(co[dn], aPl, vH[half * 2], vH[half * 2 + 1]);
                        }
                    }
                }
            }
        }
    }

    float inv0 = 1.f / l0, inv1 = 1.f / l1;
#pragma unroll
    for (int dn = 0; dn < 8; dn++) {
        int d = h * HSn + dn * 8 + (lane & 3) * 2;
#pragma unroll
        for (int half = 0; half < 2; half++) {
            int row = r0 + half * 8;
            float inv = half ? inv1 : inv0;
            float v0 = co[dn][half * 2 + 0] * inv;
            float v1 = co[dn][half * 2 + 1] * inv;
            __nv_bfloat162 hp = __floats2bfloat162_rn(v0, v1);
            __nv_bfloat162 lp = __floats2bfloat162_rn(v0 - __bfloat162float(hp.x),
                                                      v1 - __bfloat162float(hp.y));
            size_t base = ((size_t)(b * Tn + row)) * Cn + d;
            *(__nv_bfloat162*)&Oh[base] = hp;
            *(__nv_bfloat162*)&Ol[base] = lp;
        }
    }
}

// ===========================================================================
// LayerNorm v2: float4 loads, warp-shuffle reduction, packed stores.
// ===========================================================================
template <bool SPLIT>
__global__ void ln_kernel(const float* __restrict__ X, const float* __restrict__ g,
                          const float* __restrict__ be, float* __restrict__ Y,
                          __nv_bfloat16* __restrict__ Yh, __nv_bfloat16* __restrict__ Yl) {
    int row = blockIdx.x;
    int tid = threadIdx.x;
    int wid = tid >> 5;
    int lane = tid & 31;

    float4 v = *(const float4*)(X + (size_t)row * Cn + tid * 4);
    float s = v.x + v.y + v.z + v.w;
    float ss = v.x * v.x + v.y * v.y + v.z * v.z + v.w * v.w;
#pragma unroll
    for (int off = 16; off; off >>= 1) {
        s += __shfl_xor_sync(0xffffffffu, s, off);
        ss += __shfl_xor_sync(0xffffffffu, ss, off);
    }
    __shared__ float rs[8], rss[8];
    if (lane == 0) { rs[wid] = s; rss[wid] = ss; }
    __syncthreads();
    float tot = 0.f, tots = 0.f;
#pragma unroll
    for (int i = 0; i < 8; i++) { tot += rs[i]; tots += rss[i]; }

    float mean = tot * (1.f / Cn);
    float var = tots * (1.f / Cn) - mean * mean;
    float rstd = rsqrtf(var + EPSn);

    int c = tid * 4;
    float4 gv = *(const float4*)&g[c];
    float4 bev = *(const float4*)&be[c];
    float y0 = (v.x - mean) * rstd * gv.x + bev.x;
    float y1 = (v.y - mean) * rstd * gv.y + bev.y;
    float y2 = (v.z - mean) * rstd * gv.z + bev.z;
    float y3 = (v.w - mean) * rstd * gv.w + bev.w;

    if (SPLIT) {
        __nv_bfloat162 h01 = __floats2bfloat162_rn(y0, y1);
        __nv_bfloat162 h23 = __floats2bfloat162_rn(y2, y3);
        __nv_bfloat162 l01 = __floats2bfloat162_rn(y0 - __bfloat162float(h01.x),
                                                   y1 - __bfloat162float(h01.y));
        __nv_bfloat162 l23 = __floats2bfloat162_rn(y2 - __bfloat162float(h23.x),
                                                   y3 - __bfloat162float(h23.y));
        uint2 hp; hp.x = *(uint32_t*)&h01; hp.y = *(uint32_t*)&h23;
        uint2 lp; lp.x = *(uint32_t*)&l01; lp.y = *(uint32_t*)&l23;
        *(uint2*)&Yh[(size_t)row * Cn + c] = hp;
        *(uint2*)&Yl[(size_t)row * Cn + c] = lp;
    } else {
        float4 r; r.x = y0; r.y = y1; r.z = y2; r.w = y3;
        *(float4*)&Y[(size_t)row * Cn + c] = r;
    }
}

// ===========================================================================
// Launch (multi-stream fork during capture)
// ===========================================================================
static float* symaddrf(const void* sym) {
    void* p = nullptr;
    cudaGetSymbolAddress(&p, sym);
    return (float*)p;
}
static __nv_bfloat16* symaddrb(const void* sym) {
    void* p = nullptr;
    cudaGetSymbolAddress(&p, sym);
    return (__nv_bfloat16*)p;
}

extern "C" void kernel_launch(void* const* d_in, const int* in_sizes, int n_in,
                              void* d_out, int out_size) {
    const float* x   = (const float*)d_in[0];
    const float* Wq  = (const float*)d_in[1];
    const float* bq  = (const float*)d_in[2];
    const float* Wk  = (const float*)d_in[3];
    const float* bk  = (const float*)d_in[4];
    const float* Wv  = (const float*)d_in[5];
    const float* bv  = (const float*)d_in[6];
    const float* Wp  = (const float*)d_in[7];
    const float* bp  = (const float*)d_in[8];
    const float* W1  = (const float*)d_in[9];
    const float* b1  = (const float*)d_in[10];
    const float* W2  = (const float*)d_in[11];
    const float* b2  = (const float*)d_in[12];
    const float* g1  = (const float*)d_in[13];
    const float* be1 = (const float*)d_in[14];
    const float* g2  = (const float*)d_in[15];
    const float* be2 = (const float*)d_in[16];
    float* out = (float*)d_out;

    __nv_bfloat16 *xh = symaddrb(g_xh), *xl = symaddrb(g_xl);
    __nv_bfloat16 *Wqkvth = symaddrb(g_Wqkvth), *Wqkvtl = symaddrb(g_Wqkvtl);
    __nv_bfloat16 *Wpth = symaddrb(g_Wpth), *Wptl = symaddrb(g_Wptl);
    __nv_bfloat16 *W1th = symaddrb(g_W1th), *W1tl = symaddrb(g_W1tl);
    __nv_bfloat16 *W2th = symaddrb(g_W2th), *W2tl = symaddrb(g_W2tl);
    __nv_bfloat16 *qkvh = symaddrb(g_qkvh), *qkvl = symaddrb(g_qkvl);
    __nv_bfloat16 *atth = symaddrb(g_atth), *attl = symaddrb(g_attl);
    __nv_bfloat16 *hh = symaddrb(g_hh), *hl = symaddrb(g_hl);
    __nv_bfloat16 *f1h = symaddrb(g_f1h), *f1l = symaddrb(g_f1l);
    float *bqkv = symaddrf(g_bqkv);
    float *t0 = symaddrf(g_t0), *f2 = symaddrf(g_f2);

    cudaFuncSetAttribute(gemm_mma<false, false>, cudaFuncAttributeMaxDynamicSharedMemorySize, GEMM_SMEM);
    cudaFuncSetAttribute(gemm_mma<true, false>,  cudaFuncAttributeMaxDynamicSharedMemorySize, GEMM_SMEM);
    cudaFuncSetAttribute(gemm_mma<true, true>,   cudaFuncAttributeMaxDynamicSharedMemorySize, GEMM_SMEM);
    cudaFuncSetAttribute(gemm_mma<false, true>,  cudaFuncAttributeMaxDynamicSharedMemorySize, GEMM_SMEM);
    cudaFuncSetAttribute(attn_mma, cudaFuncAttributeMaxDynamicSharedMemorySize, ATT_SMEM);

    static cudaStream_t sA = nullptr, sB = nullptr;
    static cudaEvent_t eFork = nullptr, eA = nullptr, eB = nullptr;
    if (sA == nullptr) {
        cudaStreamCreateWithFlags(&sA, cudaStreamNonBlocking);
        cudaStreamCreateWithFlags(&sB, cudaStreamNonBlocking);
        cudaEventCreateWithFlags(&eFork, cudaEventDisableTiming);
        cudaEventCreateWithFlags(&eA, cudaEventDisableTiming);
        cudaEventCreateWithFlags(&eB, cudaEventDisableTiming);
    }

    const int M = Mrows;
    dim3 tb(32, 8);

    cudaEventRecord(eFork, 0);
    cudaStreamWaitEvent(sA, eFork, 0);
    cudaStreamWaitEvent(sB, eFork, 0);

    // Stream A: fused QKV weight transpose + bias concat
    transpose_split_qkv<<<dim3(HSn / 32, Cn / 32, 3 * Hn), tb, 0, sA>>>(
        Wq, Wk, Wv, bq, bk, bv, Wqkvth, Wqkvtl, bqkv);
    cudaEventRecord(eA, sA);

    // Stream B: Wp/W1/W2 transposes — overlap with QKV GEMM + attention
    transpose_split<<<dim3(Cn / 32, Cn / 32, 1), tb, 0, sB>>>(Wp, Wpth, Wptl, Cn, Cn);
    transpose_split<<<dim3(FFn / 32, Cn / 32, 1), tb, 0, sB>>>(W1, W1th, W1tl, Cn, FFn);
    transpose_split<<<dim3(Cn / 32, FFn / 32, 1), tb, 0, sB>>>(W2, W2th, W2tl, FFn, Cn);
    cudaEventRecord(eB, sB);

    // Main stream: x split runs concurrently with stream A
    split_kernel<<<(M * Cn) / 1024, 256>>>(x, xh, xl);

    cudaStreamWaitEvent(0, eA, 0);

    // 2) fused QKV projection
    gemm_mma<true, false><<<dim3(3 * Cn / 128, M / 128), 256, GEMM_SMEM>>>(
        xh, xl, Wqkvth, Wqkvtl, bqkv, nullptr, qkvh, qkvl, M, 3 * Cn, Cn);

    // 3) tensor-core flash attention
    attn_mma<<<dim3(Tn / 128, Hn, Bn), 256, ATT_SMEM>>>(qkvh, qkvl, atth, attl);

    cudaStreamWaitEvent(0, eB, 0);

    // 4) output projection
    gemm_mma<false, false><<<dim3(Cn / 128, M / 128), 256, GEMM_SMEM>>>(
        atth, attl, Wpth, Wptl, bp, t0, nullptr, nullptr, M, Cn, Cn);

    // 5) LN1 -> split
    ln_kernel<true><<<M, 256>>>(t0, g1, be1, nullptr, hh, hl);

    // 6) FFN
    gemm_mma<true, true><<<dim3(FFn / 128, M / 128), 256, GEMM_SMEM>>>(
        hh, hl, W1th, W1tl, b1, nullptr, f1h, f1l, M, FFn, Cn);
    gemm_mma<false, true><<<dim3(Cn / 128, M / 128), 256, GEMM_SMEM>>>(
        f1h, f1l, W2th, W2tl, b2, f2, nullptr, nullptr, M, Cn, FFn);

    // 7) LN2 -> output
    ln_kernel<false><<<M, 256>>>(f2, g2, be2, out, nullptr, nullptr);
}

// round 13
// speedup vs baseline: 1.0232x; 1.0232x over previous
#include <cuda_runtime.h>
#include <cuda_bf16.h>
#include <math.h>
#include <stdint.h>

// Problem constants
#define Bn 2
#define Tn 2048
#define Cn 1024
#define Hn 16
#define HSn 64
#define FFn 4096
#define EPSn 1e-5f
#define NEG_BIG (-1e30f)
#define Mrows (Bn * Tn)   // 4096
#define QKVS (3 * Cn)     // fused qkv row stride

// ===========================================================================
// PTX helpers (generic sm_80+ only)
// ===========================================================================
__device__ __forceinline__ uint32_t smem_u32(const void* p) {
    uint32_t a;
    asm("{ .reg .u64 t; cvta.to.shared.u64 t, %1; cvt.u32.u64 %0, t; }" : "=r"(a) : "l"(p));
    return a;
}

#define CP_ASYNC16(dst, src) \
    asm volatile("cp.async.cg.shared.global [%0], [%1], 16;" :: "r"(dst), "l"(src))
#define CP_ASYNC_COMMIT() asm volatile("cp.async.commit_group;" ::: "memory")
#define CP_ASYNC_WAIT0() asm volatile("cp.async.wait_group 0;" ::: "memory")
#define CP_ASYNC_WAIT1() asm volatile("cp.async.wait_group 1;" ::: "memory")

__device__ __forceinline__ void ldsm4(uint32_t r[4], uint32_t addr) {
    asm volatile("ldmatrix.sync.aligned.m8n8.x4.shared.b16 {%0,%1,%2,%3}, [%4];"
                 : "=r"(r[0]), "=r"(r[1]), "=r"(r[2]), "=r"(r[3]) : "r"(addr));
}
__device__ __forceinline__ void ldsm4t(uint32_t r[4], uint32_t addr) {
    asm volatile("ldmatrix.sync.aligned.m8n8.x4.trans.shared.b16 {%0,%1,%2,%3}, [%4];"
                 : "=r"(r[0]), "=r"(r[1]), "=r"(r[2]), "=r"(r[3]) : "r"(addr));
}

__device__ __forceinline__ void mma16816(float c[4], const uint32_t a[4],
                                         uint32_t b0, uint32_t b1) {
    asm volatile(
        "mma.sync.aligned.m16n8k16.row.col.f32.bf16.bf16.f32 "
        "{%0,%1,%2,%3}, {%4,%5,%6,%7}, {%8,%9}, {%0,%1,%2,%3};"
        : "+f"(c[0]), "+f"(c[1]), "+f"(c[2]), "+f"(c[3])
        : "r"(a[0]), "r"(a[1]), "r"(a[2]), "r"(a[3]), "r"(b0), "r"(b1));
}

__device__ __forceinline__ uint32_t sw64(uint32_t b) { return b ^ ((b >> 3) & 0x30u); }
__device__ __forceinline__ uint32_t sw128(uint32_t b) { return b ^ ((b >> 3) & 0x70u); }

// ===========================================================================
// Device scratch
// ===========================================================================
__device__ __align__(256) __nv_bfloat16 g_xh[Mrows * Cn], g_xl[Mrows * Cn];
__device__ __align__(256) __nv_bfloat16 g_Wqkvth[3 * Cn * Cn], g_Wqkvtl[3 * Cn * Cn];
__device__ __align__(256) __nv_bfloat16 g_Wpth[Cn * Cn], g_Wptl[Cn * Cn];
__device__ __align__(256) __nv_bfloat16 g_W1th[FFn * Cn], g_W1tl[FFn * Cn];
__device__ __align__(256) __nv_bfloat16 g_W2th[Cn * FFn], g_W2tl[Cn * FFn];
__device__ __align__(256) float g_bqkv[3 * Cn];
__device__ __align__(256) __nv_bfloat16 g_qkvh[Mrows * 3 * Cn], g_qkvl[Mrows * 3 * Cn];
__device__ __align__(256) __nv_bfloat16 g_atth[Mrows * Cn], g_attl[Mrows * Cn];
__device__ __align__(256) __nv_bfloat16 g_hh[Mrows * Cn], g_hl[Mrows * Cn];
__device__ __align__(256) __nv_bfloat16 g_f1h[Mrows * FFn], g_f1l[Mrows * FFn];
__device__ __align__(256) float g_t0[Mrows * Cn];
__device__ __align__(256) float g_f2[Mrows * Cn];

// ===========================================================================
// Elementwise split (vectorized x4): fp32 -> (hi, lo) bf16
// ===========================================================================
__global__ void split_kernel(const float* __restrict__ in, __nv_bfloat16* __restrict__ oh,
                             __nv_bfloat16* __restrict__ ol) {
    int i = (blockIdx.x * 256 + threadIdx.x) * 4;
    float4 v = *(const float4*)&in[i];
    __nv_bfloat162 h01 = __floats2bfloat162_rn(v.x, v.y);
    __nv_bfloat162 h23 = __floats2bfloat162_rn(v.z, v.w);
    __nv_bfloat162 l01 = __floats2bfloat162_rn(v.x - __bfloat162float(h01.x),
                                               v.y - __bfloat162float(h01.y));
    __nv_bfloat162 l23 = __floats2bfloat162_rn(v.z - __bfloat162float(h23.x),
                                               v.w - __bfloat162float(h23.y));
    uint2 hp; hp.x = *(uint32_t*)&h01; hp.y = *(uint32_t*)&h23;
    uint2 lp; lp.x = *(uint32_t*)&l01; lp.y = *(uint32_t*)&l23;
    *(uint2*)&oh[i] = hp;
    *(uint2*)&ol[i] = lp;
}

// ===========================================================================
// Tiled transpose+split (generic, used for Wp/W1/W2)
// ===========================================================================
__global__ void transpose_split(const float* __restrict__ in, __nv_bfloat16* __restrict__ oh,
                                __nv_bfloat16* __restrict__ ol, int R, int Cc) {
    __shared__ float tile[32][33];
    size_t boff = (size_t)blockIdx.z * R * Cc;
    const float* ip = in + boff;
    int i0 = blockIdx.y * 32, j0 = blockIdx.x * 32;
#pragma unroll
    for (int k = threadIdx.y; k < 32; k += 8)
        tile[k][threadIdx.x] = ip[(size_t)(i0 + k) * Cc + j0 + threadIdx.x];
    __syncthreads();
#pragma unroll
    for (int k = threadIdx.y; k < 32; k += 8) {
        float v = tile[threadIdx.x][k];
        __nv_bfloat16 h = __float2bfloat16(v);
        size_t o = boff + (size_t)(j0 + k) * R + i0 + threadIdx.x;
        oh[o] = h;
        ol[o] = __float2bfloat16(v - __bfloat162float(h));
    }
}

// ===========================================================================
// Fused QKV weight transpose+split + bias concat.
// ===========================================================================
__global__ void transpose_split_qkv(const float* __restrict__ Wq, const float* __restrict__ Wk,
                                    const float* __restrict__ Wv,
                                    const float* __restrict__ bq, const float* __restrict__ bk,
                                    const float* __restrict__ bv,
                                    __nv_bfloat16* __restrict__ oh, __nv_bfloat16* __restrict__ ol,
                                    float* __restrict__ bqkv) {
    __shared__ float tile[32][33];
    int w = blockIdx.z / Hn;
    int hz = blockIdx.z % Hn;
    const float* Win = (w == 0) ? Wq : (w == 1) ? Wk : Wv;
    const float* bin = (w == 0) ? bq : (w == 1) ? bk : bv;
    const float* ip = Win + (size_t)hz * Cn * HSn;
    __nv_bfloat16* poh = oh + (size_t)w * Cn * Cn + (size_t)hz * HSn * Cn;
    __nv_bfloat16* pol = ol + (size_t)w * Cn * Cn + (size_t)hz * HSn * Cn;

    if (blockIdx.x == 0 && blockIdx.y == 0 && hz == 0) {
        int t = threadIdx.y * 32 + threadIdx.x;
#pragma unroll
        for (int i = 0; i < 4; i++) bqkv[w * Cn + t + i * 256] = bin[t + i * 256];
    }

    int i0 = blockIdx.y * 32, j0 = blockIdx.x * 32;
#pragma unroll
    for (int k = threadIdx.y; k < 32; k += 8)
        tile[k][threadIdx.x] = ip[(size_t)(i0 + k) * HSn + j0 + threadIdx.x];
    __syncthreads();
#pragma unroll
    for (int k = threadIdx.y; k < 32; k += 8) {
        float v = tile[threadIdx.x][k];
        __nv_bfloat16 h = __float2bfloat16(v);
        size_t o = (size_t)(j0 + k) * Cn + i0 + threadIdx.x;
        poh[o] = h;
        pol[o] = __float2bfloat16(v - __bfloat162float(h));
    }
}

// ===========================================================================
// Tensor-core GEMM via mma.sync, bf16 hi/lo split (3-term fp32 emulation).
// CTA 128x128, 8 warps (4Mx2N), K-chunk 32, 3-stage cp.async, 2 CTAs/SM.
// ===========================================================================
#define STAGE_BYTES 32768
#define GEMM_SMEM (3 * STAGE_BYTES)

template <bool SPLIT, bool RELU>
__global__ void __launch_bounds__(256, 2)
gemm_mma(const __nv_bfloat16* __restrict__ Ahi, const __nv_bfloat16* __restrict__ Alo,
         const __nv_bfloat16* __restrict__ Bhi, const __nv_bfloat16* __restrict__ Blo,
         const float* __restrict__ bias,
         float* __restrict__ Cf, __nv_bfloat16* __restrict__ Chi, __nv_bfloat16* __restrict__ Clo,
         int M, int N, int K) {
    extern __shared__ char dsmem[];
    uint32_t sb = smem_u32(dsmem);

    int tid = threadIdx.x;
    int wid = tid >> 5;
    int lane = tid & 31;
    int n0 = blockIdx.x * 128;
    int m0 = blockIdx.y * 128;
    int wm = wid & 3;
    int wn = wid >> 2;

    const int NC = K >> 5;

    auto load_chunk = [&](int c, int stage) {
        uint32_t base = sb + (uint32_t)stage * STAGE_BYTES;
        size_t kof = (size_t)c * 32;
#pragma unroll
        for (int i = 0; i < 8; i++) {
            int g = i * 256 + tid;
            int tilei = g >> 9;
            int idx = g & 511;
            int row = idx >> 2;
            int ch = idx & 3;
            const __nv_bfloat16* src;
            if (tilei == 0)      src = Ahi + (size_t)(m0 + row) * K + kof + ch * 8;
            else if (tilei == 1) src = Alo + (size_t)(m0 + row) * K + kof + ch * 8;
            else if (tilei == 2) src = Bhi + (size_t)(n0 + row) * K + kof + ch * 8;
            else                 src = Blo + (size_t)(n0 + row) * K + kof + ch * 8;
            uint32_t dst = base + (uint32_t)tilei * 8192u + sw64((uint32_t)(row * 64 + ch * 16));
            CP_ASYNC16(dst, src);
        }
        CP_ASYNC_COMMIT();
    };

    float c[2][8][4];
#pragma unroll
    for (int mt = 0; mt < 2; mt++)
#pragma unroll
        for (int nt = 0; nt < 8; nt++)
#pragma unroll
            for (int j = 0; j < 4; j++) c[mt][nt][j] = 0.f;

    load_chunk(0, 0);
    load_chunk(1, 1);

    int arow = lane & 15;
    int aoff = (lane >> 4) * 16;
    int brow = ((lane >> 4) << 3) + (lane & 7);
    int boff = ((lane >> 3) & 1) * 16;

    for (int cc = 0; cc < NC; cc++) {
        if (cc == NC - 1) { CP_ASYNC_WAIT0(); } else { CP_ASYNC_WAIT1(); }
        __syncthreads();
        if (cc + 2 < NC) load_chunk(cc + 2, (cc + 2) % 3);

        uint32_t base = sb + (uint32_t)(cc % 3) * STAGE_BYTES;
#pragma unroll
        for (int k16 = 0; k16 < 2; k16++) {
            uint32_t ahi[2][4], alo[2][4];
#pragma unroll
            for (int mt = 0; mt < 2; mt++) {
                uint32_t byte = (uint32_t)((wm * 32 + mt * 16 + arow) * 64 + k16 * 32 + aoff);
                uint32_t sw = sw64(byte);
                ldsm4(ahi[mt], base + sw);
                ldsm4(alo[mt], base + 8192u + sw);
            }
#pragma unroll
            for (int nt16 = 0; nt16 < 4; nt16++) {
                uint32_t byte = (uint32_t)((wn * 64 + nt16 * 16 + brow) * 64 + k16 * 32 + boff);
                uint32_t sw = sw64(byte);
                uint32_t bh[4], bl[4];
                ldsm4(bh, base + 16384u + sw);
                ldsm4(bl, base + 24576u + sw);
#pragma unroll
                for (int term = 0; term < 3; term++) {
#pragma unroll
                    for (int half = 0; half < 2; half++) {
                        int nt = nt16 * 2 + half;
#pragma unroll
                        for (int mt = 0; mt < 2; mt++) {
                            if (term == 0)      mma16816(c[mt][nt], ahi[mt], bh[half * 2], bh[half * 2 + 1]);
                            else if (term == 1) mma16816(c[mt][nt], ahi[mt], bl[half * 2], bl[half * 2 + 1]);
                            else                mma16816(c[mt][nt], alo[mt], bh[half * 2], bh[half * 2 + 1]);
                        }
                    }
                }
            }
        }
    }

    int mbase = m0 + wm * 32;
    int nbase = n0 + wn * 64;
#pragma unroll
    for (int mt = 0; mt < 2; mt++) {
#pragma unroll
        for (int nt = 0; nt < 8; nt++) {
            int row0 = mbase + mt * 16 + (lane >> 2);
            int col = nbase + nt * 8 + (lane & 3) * 2;
            float b0 = bias[col], b1 = bias[col + 1];
#pragma unroll
            for (int half = 0; half < 2; half++) {
                int row = row0 + half * 8;
                float v0 = c[mt][nt][half * 2 + 0] + b0;
                float v1 = c[mt][nt][half * 2 + 1] + b1;
                if (RELU) { v0 = fmaxf(v0, 0.f); v1 = fmaxf(v1, 0.f); }
                if (SPLIT) {
                    __nv_bfloat16 h0 = __float2bfloat16(v0);
                    __nv_bfloat16 h1 = __float2bfloat16(v1);
                    __nv_bfloat162 hp; hp.x = h0; hp.y = h1;
                    __nv_bfloat162 lp;
                    lp.x = __float2bfloat16(v0 - __bfloat162float(h0));
                    lp.y = __float2bfloat16(v1 - __bfloat162float(h1));
                    *(__nv_bfloat162*)&Chi[(size_t)row * N + col] = hp;
                    *(__nv_bfloat162*)&Clo[(size_t)row * N + col] = lp;
                } else {
                    float2 r; r.x = v0; r.y = v1;
                    *(float2*)&Cf[(size_t)row * N + col] = r;
                }
            }
        }
    }
}

// ===========================================================================
// Tensor-core flash attention (R11 config: Q-hi cached in regs, Q-lo ldsm),
// bf16 split emulation, double-buffered KV, base-2 softmax, heavy-first.
// ===========================================================================
#define ATT_SMEM 98304

__global__ void __launch_bounds__(256, 2) attn_mma(
    const __nv_bfloat16* __restrict__ QKVh, const __nv_bfloat16* __restrict__ QKVl,
    __nv_bfloat16* __restrict__ Oh, __nv_bfloat16* __restrict__ Ol) {
    extern __shared__ char dsmem[];
    uint32_t sbQ = smem_u32(dsmem);
    uint32_t sbKV = sbQ + 32768u;

    int tid = threadIdx.x;
    int wid = tid >> 5;
    int lane = tid & 31;
    int q0 = ((int)gridDim.x - 1 - (int)blockIdx.x) * 128;   // heavy tiles first
    int h = blockIdx.y;
    int b = blockIdx.z;

    const __nv_bfloat16* Qhg = QKVh + ((size_t)(b * Tn + q0)) * QKVS + h * HSn;
    const __nv_bfloat16* Qlg = QKVl + ((size_t)(b * Tn + q0)) * QKVS + h * HSn;
    const __nv_bfloat16* Khg = QKVh + ((size_t)(b * Tn)) * QKVS + Cn + h * HSn;
    const __nv_bfloat16* Klg = QKVl + ((size_t)(b * Tn)) * QKVS + Cn + h * HSn;
    const __nv_bfloat16* Vhg = QKVh + ((size_t)(b * Tn)) * QKVS + 2 * Cn + h * HSn;
    const __nv_bfloat16* Vlg = QKVl + ((size_t)(b * Tn)) * QKVS + 2 * Cn + h * HSn;

    auto load_kv = [&](int t) {
        int s0 = t * 64;
        uint32_t stb = sbKV + (uint32_t)(t & 1) * 32768u;
#pragma unroll
        for (int i = 0; i < 8; i++) {
            int g = i * 256 + tid;
            int mat = g >> 9;
            int idx = g & 511;
            int row = idx >> 3;
            int ch = idx & 7;
            const __nv_bfloat16* src;
            if (mat == 0)      src = Khg + (size_t)(s0 + row) * QKVS + ch * 8;
            else if (mat == 1) src = Klg + (size_t)(s0 + row) * QKVS + ch * 8;
            else if (mat == 2) src = Vhg + (size_t)(s0 + row) * QKVS + ch * 8;
            else               src = Vlg + (size_t)(s0 + row) * QKVS + ch * 8;
            CP_ASYNC16(stb + (uint32_t)mat * 8192u + sw128((uint32_t)(row * 128 + ch * 16)), src);
        }
        CP_ASYNC_COMMIT();
    };

    // Q (hi/lo) load in its own group, then first KV tile
#pragma unroll
    for (int i = 0; i < 8; i++) {
        int g = i * 256 + tid;
        int hilo = g >> 10;
        int idx = g & 1023;
        int row = idx >> 3;
        int ch = idx & 7;
        const __nv_bfloat16* src = (hilo ? Qlg : Qhg) + (size_t)row * QKVS + ch * 8;
        CP_ASYNC16(sbQ + (uint32_t)hilo * 16384u + sw128((uint32_t)(row * 128 + ch * 16)), src);
    }
    CP_ASYNC_COMMIT();
    load_kv(0);

    int arow = lane & 15;
    int aoff = (lane >> 4) * 16;
    int brow = ((lane >> 4) << 3) + (lane & 7);
    int boff = ((lane >> 3) & 1) * 16;
    int vrow = ((lane >> 3) & 1) * 8 + (lane & 7);
    int vcol = (lane >> 4) * 8;

    // Wait Q group, then hold Q-hi frags in registers (Q-lo stays in smem)
    CP_ASYNC_WAIT1();
    __syncthreads();
    uint32_t qfh[4][4];
#pragma unroll
    for (int kk = 0; kk < 4; kk++) {
        uint32_t abyte = (uint32_t)((wid * 16 + arow) * 128 + kk * 32 + aoff);
        ldsm4(qfh[kk], sbQ + sw128(abyte));
    }

    float m0s = NEG_BIG, m1s = NEG_BIG, l0 = 0.f, l1 = 0.f;
    float co[8][4];
#pragma unroll
    for (int nt = 0; nt < 8; nt++)
#pragma unroll
        for (int j = 0; j < 4; j++) co[nt][j] = 0.f;

    int rw = q0 + wid * 16;
    int r0 = rw + (lane >> 2);
    int nkt = q0 / 64 + 2;
    const float scale2 = 0.125f * 1.44269504089f;   // base-2 softmax

    for (int t = 0; t < nkt; t++) {
        __syncthreads();
        if (t + 1 < nkt) { load_kv(t + 1); CP_ASYNC_WAIT1(); }
        else             { CP_ASYNC_WAIT0(); }
        __syncthreads();

        int s0 = t * 64;
        uint32_t sbK = sbKV + (uint32_t)(t & 1) * 32768u;
        uint32_t sbV = sbK + 16384u;

        if (s0 <= rw + 15) {
            float sp[8][4];
#pragma unroll
            for (int nt = 0; nt < 8; nt++)
#pragma unroll
                for (int j = 0; j < 4; j++) sp[nt][j] = 0.f;

#pragma unroll
            for (int kk = 0; kk < 4; kk++) {
                uint32_t abyte = (uint32_t)((wid * 16 + arow) * 128 + kk * 32 + aoff);
                uint32_t aL[4];
                ldsm4(aL, sbQ + 16384u + sw128(abyte));
#pragma unroll
                for (int nt16 = 0; nt16 < 4; nt16++) {
                    uint32_t bbyte = (uint32_t)((nt16 * 16 + brow) * 128 + kk * 32 + boff);
                    uint32_t bH[4], bL[4];
                    ldsm4(bH, sbK + sw128(bbyte));
                    ldsm4(bL, sbK + 8192u + sw128(bbyte));
#pragma unroll
                    for (int term = 0; term < 3; term++) {
#pragma unroll
                        for (int half = 0; half < 2; half++) {
                            int nt = nt16 * 2 + half;
                            if (term == 0)      mma16816(sp[nt], qfh[kk], bH[half * 2], bH[half * 2 + 1]);
                            else if (term == 1) mma16816(sp[nt], qfh[kk], bL[half * 2], bL[half * 2 + 1]);
                            else                mma16816(sp[nt], aL, bH[half * 2], bH[half * 2 + 1]);
                        }
                    }
                }
            }

            bool diag = (s0 + 63 > rw);
            float mx0 = NEG_BIG, mx1 = NEG_BIG;
#pragma unroll
            for (int nt = 0; nt < 8; nt++) {
                float c0 = sp[nt][0] * scale2;
                float c1 = sp[nt][1] * scale2;
                float c2 = sp[nt][2] * scale2;
                float c3 = sp[nt][3] * scale2;
                if (diag) {
                    int cg = s0 + nt * 8 + (lane & 3) * 2;
                    if (cg > r0) c0 = NEG_BIG;
                    if (cg + 1 > r0) c1 = NEG_BIG;
                    if (cg > r0 + 8) c2 = NEG_BIG;
                    if (cg + 1 > r0 + 8) c3 = NEG_BIG;
                }
                sp[nt][0] = c0; sp[nt][1] = c1; sp[nt][2] = c2; sp[nt][3] = c3;
                mx0 = fmaxf(mx0, fmaxf(c0, c1));
                mx1 = fmaxf(mx1, fmaxf(c2, c3));
            }
            mx0 = fmaxf(mx0, __shfl_xor_sync(0xffffffffu, mx0, 1));
            mx0 = fmaxf(mx0, __shfl_xor_sync(0xffffffffu, mx0, 2));
            mx1 = fmaxf(mx1, __shfl_xor_sync(0xffffffffu, mx1, 1));
            mx1 = fmaxf(mx1, __shfl_xor_sync(0xffffffffu, mx1, 2));

            float mn0 = fmaxf(m0s, mx0), mn1 = fmaxf(m1s, mx1);
            float al0 = exp2f(m0s - mn0), al1 = exp2f(m1s - mn1);
            m0s = mn0; m1s = mn1;

            float ps0 = 0.f, ps1 = 0.f;
#pragma unroll
            for (int nt = 0; nt < 8; nt++) {
                float p0 = exp2f(sp[nt][0] - mn0);
                float p1 = exp2f(sp[nt][1] - mn0);
                float p2 = exp2f(sp[nt][2] - mn1);
                float p3 = exp2f(sp[nt][3] - mn1);
                ps0 += p0 + p1; ps1 += p2 + p3;
                sp[nt][0] = p0; sp[nt][1] = p1; sp[nt][2] = p2; sp[nt][3] = p3;
            }
            ps0 += __shfl_xor_sync(0xffffffffu, ps0, 1);
            ps0 += __shfl_xor_sync(0xffffffffu, ps0, 2);
            ps1 += __shfl_xor_sync(0xffffffffu, ps1, 1);
            ps1 += __shfl_xor_sync(0xffffffffu, ps1, 2);
            l0 = l0 * al0 + ps0;
            l1 = l1 * al1 + ps1;
#pragma unroll
            for (int nt = 0; nt < 8; nt++) {
                co[nt][0] *= al0; co[nt][1] *= al0;
                co[nt][2] *= al1; co[nt][3] *= al1;
            }

#pragma unroll
            for (int kk = 0; kk < 4; kk++) {
                uint32_t aPh[4], aPl[4];
#pragma unroll
                for (int q = 0; q < 2; q++) {
                    int nt = 2 * kk + q;
#pragma unroll
                    for (int rr = 0; rr < 2; rr++) {
                        float v0 = sp[nt][rr * 2 + 0];
                        float v1 = sp[nt][rr * 2 + 1];
                        __nv_bfloat162 hp = __floats2bfloat162_rn(v0, v1);
                        float r0f = v0 - __bfloat162float(hp.x);
                        float r1f = v1 - __bfloat162float(hp.y);
                        __nv_bfloat162 lp = __floats2bfloat162_rn(r0f, r1f);
                        aPh[q * 2 + rr] = *(uint32_t*)&hp;
                        aPl[q * 2 + rr] = *(uint32_t*)&lp;
                    }
                }
#pragma unroll
                for (int dnt16 = 0; dnt16 < 4; dnt16++) {
                    uint32_t vbyte = (uint32_t)((kk * 16 + vrow) * 128 + (dnt16 * 16 + vcol) * 2);
                    uint32_t vH[4], vL[4];
                    ldsm4t(vH, sbV + sw128(vbyte));
                    ldsm4t(vL, sbV + 8192u + sw128(vbyte));
#pragma unroll
                    for (int term = 0; term < 3; term++) {
#pragma unroll
                        for (int half = 0; half < 2; half++) {
                            int dn = dnt16 * 2 + half;
                            if (term == 0)      mma16816(co[dn], aPh, vH[half * 2], vH[half * 2 + 1]);
                            else if (term == 1) mma16816(co[dn], aPh, vL[half * 2], vL[half * 2 + 1]);
                            else                mma16816(co[dn], aPl, vH[half * 2], vH[half * 2 + 1]);
                        }
                    }
                }
            }
        }
    }

    float inv0 = 1.f / l0, inv1 = 1.f / l1;
#pragma unroll
    for (int dn = 0; dn < 8; dn++) {
        int d = h * HSn + dn * 8 + (lane & 3) * 2;
#pragma unroll
        for (int half = 0; half < 2; half++) {
            int row = r0 + half * 8;
            float inv = half ? inv1 : inv0;
            float v0 = co[dn][half * 2 + 0] * inv;
            float v1 = co[dn][half * 2 + 1] * inv;
            __nv_bfloat162 hp = __floats2bfloat162_rn(v0, v1);
            __nv_bfloat162 lp = __floats2bfloat162_rn(v0 - __bfloat162float(hp.x),
                                                      v1 - __bfloat162float(hp.y));
            size_t base = ((size_t)(b * Tn + row)) * Cn + d;
            *(__nv_bfloat162*)&Oh[base] = hp;
            *(__nv_bfloat162*)&Ol[base] = lp;
        }
    }
}

// ===========================================================================
// LayerNorm v2: float4 loads, warp-shuffle reduction, packed stores.
// ===========================================================================
template <bool SPLIT>
__global__ void ln_kernel(const float* __restrict__ X, const float* __restrict__ g,
                          const float* __restrict__ be, float* __restrict__ Y,
                          __nv_bfloat16* __restrict__ Yh, __nv_bfloat16* __restrict__ Yl) {
    int row = blockIdx.x;
    int tid = threadIdx.x;
    int wid = tid >> 5;
    int lane = tid & 31;

    float4 v = *(const float4*)(X + (size_t)row * Cn + tid * 4);
    float s = v.x + v.y + v.z + v.w;
    float ss = v.x * v.x + v.y * v.y + v.z * v.z + v.w * v.w;
#pragma unroll
    for (int off = 16; off; off >>= 1) {
        s += __shfl_xor_sync(0xffffffffu, s, off);
        ss += __shfl_xor_sync(0xffffffffu, ss, off);
    }
    __shared__ float rs[8], rss[8];
    if (lane == 0) { rs[wid] = s; rss[wid] = ss; }
    __syncthreads();
    float tot = 0.f, tots = 0.f;
#pragma unroll
    for (int i = 0; i < 8; i++) { tot += rs[i]; tots += rss[i]; }

    float mean = tot * (1.f / Cn);
    float var = tots * (1.f / Cn) - mean * mean;
    float rstd = rsqrtf(var + EPSn);

    int c = tid * 4;
    float4 gv = *(const float4*)&g[c];
    float4 bev = *(const float4*)&be[c];
    float y0 = (v.x - mean) * rstd * gv.x + bev.x;
    float y1 = (v.y - mean) * rstd * gv.y + bev.y;
    float y2 = (v.z - mean) * rstd * gv.z + bev.z;
    float y3 = (v.w - mean) * rstd * gv.w + bev.w;

    if (SPLIT) {
        __nv_bfloat162 h01 = __floats2bfloat162_rn(y0, y1);
        __nv_bfloat162 h23 = __floats2bfloat162_rn(y2, y3);
        __nv_bfloat162 l01 = __floats2bfloat162_rn(y0 - __bfloat162float(h01.x),
                                                   y1 - __bfloat162float(h01.y));
        __nv_bfloat162 l23 = __floats2bfloat162_rn(y2 - __bfloat162float(h23.x),
                                                   y3 - __bfloat162float(h23.y));
        uint2 hp; hp.x = *(uint32_t*)&h01; hp.y = *(uint32_t*)&h23;
        uint2 lp; lp.x = *(uint32_t*)&l01; lp.y = *(uint32_t*)&l23;
        *(uint2*)&Yh[(size_t)row * Cn + c] = hp;
        *(uint2*)&Yl[(size_t)row * Cn + c] = lp;
    } else {
        float4 r; r.x = y0; r.y = y1; r.z = y2; r.w = y3;
        *(float4*)&Y[(size_t)row * Cn + c] = r;
    }
}

// ===========================================================================
// Launch (multi-stream fork during capture)
// ===========================================================================
static float* symaddrf(const void* sym) {
    void* p = nullptr;
    cudaGetSymbolAddress(&p, sym);
    return (float*)p;
}
static __nv_bfloat16* symaddrb(const void* sym) {
    void* p = nullptr;
    cudaGetSymbolAddress(&p, sym);
    return (__nv_bfloat16*)p;
}

extern "C" void kernel_launch(void* const* d_in, const int* in_sizes, int n_in,
                              void* d_out, int out_size) {
    const float* x   = (const float*)d_in[0];
    const float* Wq  = (const float*)d_in[1];
    const float* bq  = (const float*)d_in[2];
    const float* Wk  = (const float*)d_in[3];
    const float* bk  = (const float*)d_in[4];
    const float* Wv  = (const float*)d_in[5];
    const float* bv  = (const float*)d_in[6];
    const float* Wp  = (const float*)d_in[7];
    const float* bp  = (const float*)d_in[8];
    const float* W1  = (const float*)d_in[9];
    const float* b1  = (const float*)d_in[10];
    const float* W2  = (const float*)d_in[11];
    const float* b2  = (const float*)d_in[12];
    const float* g1  = (const float*)d_in[13];
    const float* be1 = (const float*)d_in[14];
    const float* g2  = (const float*)d_in[15];
    const float* be2 = (const float*)d_in[16];
    float* out = (float*)d_out;

    __nv_bfloat16 *xh = symaddrb(g_xh), *xl = symaddrb(g_xl);
    __nv_bfloat16 *Wqkvth = symaddrb(g_Wqkvth), *Wqkvtl = symaddrb(g_Wqkvtl);
    __nv_bfloat16 *Wpth = symaddrb(g_Wpth), *Wptl = symaddrb(g_Wptl);
    __nv_bfloat16 *W1th = symaddrb(g_W1th), *W1tl = symaddrb(g_W1tl);
    __nv_bfloat16 *W2th = symaddrb(g_W2th), *W2tl = symaddrb(g_W2tl);
    __nv_bfloat16 *qkvh = symaddrb(g_qkvh), *qkvl = symaddrb(g_qkvl);
    __nv_bfloat16 *atth = symaddrb(g_atth), *attl = symaddrb(g_attl);
    __nv_bfloat16 *hh = symaddrb(g_hh), *hl = symaddrb(g_hl);
    __nv_bfloat16 *f1h = symaddrb(g_f1h), *f1l = symaddrb(g_f1l);
    float *bqkv = symaddrf(g_bqkv);
    float *t0 = symaddrf(g_t0), *f2 = symaddrf(g_f2);

    cudaFuncSetAttribute(gemm_mma<false, false>, cudaFuncAttributeMaxDynamicSharedMemorySize, GEMM_SMEM);
    cudaFuncSetAttribute(gemm_mma<true, false>,  cudaFuncAttributeMaxDynamicSharedMemorySize, GEMM_SMEM);
    cudaFuncSetAttribute(gemm_mma<true, true>,   cudaFuncAttributeMaxDynamicSharedMemorySize, GEMM_SMEM);
    cudaFuncSetAttribute(gemm_mma<false, true>,  cudaFuncAttributeMaxDynamicSharedMemorySize, GEMM_SMEM);
    cudaFuncSetAttribute(attn_mma, cudaFuncAttributeMaxDynamicSharedMemorySize, ATT_SMEM);

    static cudaStream_t sA = nullptr, sB = nullptr;
    static cudaEvent_t eFork = nullptr, eA = nullptr, eB = nullptr;
    if (sA == nullptr) {
        cudaStreamCreateWithFlags(&sA, cudaStreamNonBlocking);
        cudaStreamCreateWithFlags(&sB, cudaStreamNonBlocking);
        cudaEventCreateWithFlags(&eFork, cudaEventDisableTiming);
        cudaEventCreateWithFlags(&eA, cudaEventDisableTiming);
        cudaEventCreateWithFlags(&eB, cudaEventDisableTiming);
    }

    const int M = Mrows;
    dim3 tb(32, 8);

    cudaEventRecord(eFork, 0);
    cudaStreamWaitEvent(sA, eFork, 0);
    cudaStreamWaitEvent(sB, eFork, 0);

    // Stream A: fused QKV weight transpose + bias concat
    transpose_split_qkv<<<dim3(HSn / 32, Cn / 32, 3 * Hn), tb, 0, sA>>>(
        Wq, Wk, Wv, bq, bk, bv, Wqkvth, Wqkvtl, bqkv);
    cudaEventRecord(eA, sA);

    // Stream B: Wp/W1/W2 transposes — overlap with QKV GEMM + attention
    transpose_split<<<dim3(Cn / 32, Cn / 32, 1), tb, 0, sB>>>(Wp, Wpth, Wptl, Cn, Cn);
    transpose_split<<<dim3(FFn / 32, Cn / 32, 1), tb, 0, sB>>>(W1, W1th, W1tl, Cn, FFn);
    transpose_split<<<dim3(Cn / 32, FFn / 32, 1), tb, 0, sB>>>(W2, W2th, W2tl, FFn, Cn);
    cudaEventRecord(eB, sB);

    // Main stream: x split runs concurrently with stream A
    split_kernel<<<(M * Cn) / 1024, 256>>>(x, xh, xl);

    cudaStreamWaitEvent(0, eA, 0);

    // 2) fused QKV projection
    gemm_mma<true, false><<<dim3(3 * Cn / 128, M / 128), 256, GEMM_SMEM>>>(
        xh, xl, Wqkvth, Wqkvtl, bqkv, nullptr, qkvh, qkvl, M, 3 * Cn, Cn);

    // 3) tensor-core flash attention
    attn_mma<<<dim3(Tn / 128, Hn, Bn), 256, ATT_SMEM>>>(qkvh, qkvl, atth, attl);

    cudaStreamWaitEvent(0, eB, 0);

    // 4) output projection
    gemm_mma<false, false><<<dim3(Cn / 128, M / 128), 256, GEMM_SMEM>>>(
        atth, attl, Wpth, Wptl, bp, t0, nullptr, nullptr, M, Cn, Cn);

    // 5) LN1 -> split
    ln_kernel<true><<<M, 256>>>(t0, g1, be1, nullptr, hh, hl);

    // 6) FFN
    gemm_mma<true, true><<<dim3(FFn / 128, M / 128), 256, GEMM_SMEM>>>(
        hh, hl, W1th, W1tl, b1, nullptr, f1h, f1l, M, FFn, Cn);
    gemm_mma<false, true><<<dim3(Cn / 128, M / 128), 256, GEMM_SMEM>>>(
        f1h, f1l, W2th, W2tl, b2, f2, nullptr, nullptr, M, Cn, FFn);

    // 7) LN2 -> output
    ln_kernel<false><<<M, 256>>>(f2, g2, be2, out, nullptr, nullptr);
}